// round 16
// baseline (speedup 1.0000x reference)
#include <cuda_runtime.h>
#include <cuda_fp16.h>
#include <cstdint>

// ResidualNet: hash-grid encode (4 levels, T=2^19, F=2) + MLP 8->64->64->1
//   d_in[0] xyz [N,3] f32 (N=2,000,000), d_in[1] tables [4,524288,2] f32,
//   d_in[2] W_in [8,64], d_in[3] W_h [64,64], d_in[4] W_out [64,1]
// Output: sdf [N] f32
//
// encode_kernel (round-14 proven gather body): high-occupancy gather with
//   x-pair LDG.128 merge (ux even => idx(ux+1)==idx(ux)^1), f16 hi/lo out.
//   First 14 CTAs additionally build the B-fragment images (prep folded in;
//   ready at kernel boundary, before mlp launches).
// mlp_kernel (round-14 proven): grid-stride HMMA hi/lo-split MLP,
//   fragments staged once per CTA.

#define TSIZE (1u << 19)
#define TMASK (TSIZE - 1u)
#define P2 2654435761u
#define P3 805459861u
#define NMAX  2000000

// staged enc: per point 8 u32 = [ehi0..3, elo0..3] (f16x2 each)
static __device__ __align__(16) uint32_t g_enc[(size_t)NMAX * 8];
// precomputed B fragments: 112 slots (B1: slots 0..15; B2: 16 + t*8 + n)
static __device__ __align__(16) uint2 g_frags[112 * 32];

__device__ __forceinline__ float leaky(float v) { return fmaxf(v, 0.01f * v); }

__device__ __forceinline__ uint32_t pack_f16x2(float lo, float hi) {
    uint32_t r;
    asm("cvt.rn.f16x2.f32 %0, %1, %2;" : "=r"(r) : "f"(hi), "f"(lo));
    return r;
}
__device__ __forceinline__ void unpack_f16x2(uint32_t v, float& lo, float& hi) {
    asm("{ .reg .f16 a,b; mov.b32 {a,b}, %2; cvt.f32.f16 %0, a; cvt.f32.f16 %1, b; }"
        : "=f"(lo), "=f"(hi) : "r"(v));
}

__device__ __forceinline__ void mma16816(float* d,
                                         uint32_t a0, uint32_t a1, uint32_t a2, uint32_t a3,
                                         uint32_t b0, uint32_t b1) {
    asm volatile("mma.sync.aligned.m16n8k16.row.col.f32.f16.f16.f32 "
                 "{%0,%1,%2,%3}, {%4,%5,%6,%7}, {%8,%9}, {%0,%1,%2,%3};"
                 : "+f"(d[0]), "+f"(d[1]), "+f"(d[2]), "+f"(d[3])
                 : "r"(a0), "r"(a1), "r"(a2), "r"(a3), "r"(b0), "r"(b1));
}

// Build one B-fragment slot element (prep work, folded into encode).
// B1 expanded K=32 rows: [hi(W_in), hi(W_in), lo(W_in), 0]  (A1=[hi,lo,hi,0])
// B2 expanded K=192:     [hi(W_h), hi(W_h), lo(W_h)]        (A2=[hi,lo,hi])
__device__ void build_frag(int idx, const float* __restrict__ W_in,
                           const float* __restrict__ W_h)
{
    int lane = idx & 31, s = idx >> 5;
    int n = (s & 7) * 8 + (lane >> 2);
    uint32_t b[2];
    #pragma unroll
    for (int w = 0; w < 2; w++) {
        __half hv[2];
        #pragma unroll
        for (int e = 0; e < 2; e++) {
            int kr = (lane & 3) * 2 + e + w * 8;
            float val = 0.0f;
            bool want_lo = false;
            bool zero = false;
            if (s < 16) {
                int kk = (s >> 3) * 16 + kr;             // 0..31
                if (kk < 8)       val = W_in[kk * 64 + n];
                else if (kk < 16) val = W_in[(kk - 8) * 64 + n];
                else if (kk < 24) { val = W_in[(kk - 16) * 64 + n]; want_lo = true; }
                else zero = true;
            } else {
                int kk = ((s - 16) >> 3) * 16 + kr;      // 0..191
                if (kk < 64)       val = W_h[kk * 64 + n];
                else if (kk < 128) val = W_h[(kk - 64) * 64 + n];
                else { val = W_h[(kk - 128) * 64 + n]; want_lo = true; }
            }
            __half h = __float2half_rn(val);
            if (want_lo) h = __float2half_rn(val - __half2float(h));
            if (zero) h = __float2half_rn(0.0f);
            hv[e] = h;
        }
        __half2 hh = __halves2half2(hv[0], hv[1]);
        b[w] = *reinterpret_cast<uint32_t*>(&hh);
    }
    g_frags[idx] = make_uint2(b[0], b[1]);
}

// ---------------------------------------------------------------------------
// encode: hash-grid gather with x-pair merge, emit f16 hi/lo enc.
// CTAs 0..13 also build the 3584 fragment slots (one per thread).
// ---------------------------------------------------------------------------
extern "C" __global__ void __launch_bounds__(256, 4)
encode_kernel(const float* __restrict__ xyz,
              const float* __restrict__ tables,
              const float* __restrict__ W_in,
              const float* __restrict__ W_h,
              int N)
{
    // folded prep: first 14 CTAs, one fragment element per thread
    if (blockIdx.x < 14) {
        build_frag(blockIdx.x * 256 + threadIdx.x, W_in, W_h);
    }

    int i = blockIdx.x * 256 + threadIdx.x;
    if (i >= N) return;

    float px = (xyz[3 * i + 0] + 5.0f) / 10.0f;
    float py = (xyz[3 * i + 1] + 5.0f) / 10.0f;
    float pz = (xyz[3 * i + 2] + 5.0f) / 10.0f;

    float enc[8];
    #pragma unroll
    for (int l = 0; l < 4; l++) {
        float res = (float)(200 << l);
        float fx = px * res, fy = py * res, fz = pz * res;
        float bx = floorf(fx), by = floorf(fy), bz = floorf(fz);
        float tx = fx - bx, ty = fy - by, tz = fz - bz;
        unsigned ux = (unsigned)bx, uy = (unsigned)by, uz = (unsigned)bz;
        const float2* tab = (const float2*)(tables + (size_t)l * TSIZE * 2u);
        float wx0 = 1.0f - tx, wx1 = tx;
        float wy[2] = {1.0f - ty, ty};
        float wz[2] = {1.0f - tz, tz};
        unsigned Ky[2] = {uy * P2, (uy + 1) * P2};
        unsigned Kz[2] = {uz * P3, (uz + 1) * P3};
        const bool even = (ux & 1u) == 0u;

        float f0 = 0.0f, f1 = 0.0f;
        #pragma unroll
        for (int yy = 0; yy < 2; yy++) {
            #pragma unroll
            for (int zz = 0; zz < 2; zz++) {
                unsigned K = Ky[yy] ^ Kz[zz];
                unsigned i0 = (ux ^ K) & TMASK;
                float2 fa, fb;
                if (even) {
                    // idx(ux+1) = i0 ^ 1: both corners in one 16B-aligned pair
                    unsigned e = i0 & ~1u;
                    float4 v = __ldg((const float4*)(tab + e));
                    bool swp = (i0 & 1u) != 0u;
                    fa = swp ? make_float2(v.z, v.w) : make_float2(v.x, v.y);
                    fb = swp ? make_float2(v.x, v.y) : make_float2(v.z, v.w);
                } else {
                    unsigned i1 = ((ux + 1u) ^ K) & TMASK;
                    fa = __ldg(tab + i0);
                    fb = __ldg(tab + i1);
                }
                float wyz = wy[yy] * wz[zz];
                float wa = wx0 * wyz, wb = wx1 * wyz;
                f0 = fmaf(fa.x, wa, fmaf(fb.x, wb, f0));
                f1 = fmaf(fa.y, wa, fmaf(fb.y, wb, f1));
            }
        }
        enc[2 * l + 0] = f0;
        enc[2 * l + 1] = f1;
    }

    uint32_t eh[4], el[4];
    #pragma unroll
    for (int c = 0; c < 4; c++) {
        float x0 = enc[2 * c], x1 = enc[2 * c + 1];
        eh[c] = pack_f16x2(x0, x1);
        float h0, h1;
        unpack_f16x2(eh[c], h0, h1);
        el[c] = pack_f16x2(x0 - h0, x1 - h1);
    }
    uint4* o = (uint4*)&g_enc[(size_t)i * 8];
    o[0] = make_uint4(eh[0], eh[1], eh[2], eh[3]);
    o[1] = make_uint4(el[0], el[1], el[2], el[3]);
}

// ---------------------------------------------------------------------------
// mlp: GRID-STRIDE over 128-point tiles; 32 points/warp, mma.sync m16n8k16.
// Fragments staged ONCE per CTA.
// ---------------------------------------------------------------------------
extern "C" __global__ void __launch_bounds__(128, 2)
mlp_kernel(const float* __restrict__ W_out, float* __restrict__ out,
           int N, int numTiles)
{
    __shared__ uint2 sF[112 * 32];   // 28 KB B fragments

    const int tid = threadIdx.x;
    const int lane = tid & 31;
    const int wid = tid >> 5;

    // stage fragments once
    {
        const uint4* s = (const uint4*)g_frags;
        uint4* d = (uint4*)sF;
        #pragma unroll
        for (int k = tid; k < 112 * 32 / 2; k += 128) d[k] = s[k];
    }

    // W_out per-lane registers (loop-invariant)
    float wo0[8], wo1[8];
    #pragma unroll
    for (int j = 0; j < 8; j++) {
        float2 v = __ldg((const float2*)&W_out[j * 8 + (lane & 3) * 2]);
        wo0[j] = v.x; wo1[j] = v.y;
    }
    __syncthreads();  // fragments staged

    const bool b0sel = (lane & 1), b1sel = (lane & 2);

    for (int tile = blockIdx.x; tile < numTiles; tile += gridDim.x) {
        int i = tile * 128 + tid;
        int ic = i < N ? i : (N - 1);
        const uint4* ep = (const uint4*)&g_enc[(size_t)ic * 8];
        uint4 EH = ep[0], EL = ep[1];
        uint32_t ehi[4] = {EH.x, EH.y, EH.z, EH.w};
        uint32_t elo[4] = {EL.x, EL.y, EL.z, EL.w};

        // ---- build A1 fragment pieces via shuffles ----
        uint32_t Ah[2][2], Al[2][2];
        #pragma unroll
        for (int m = 0; m < 2; m++) {
            #pragma unroll
            for (int h = 0; h < 2; h++) {
                int src = m * 16 + h * 8 + (lane >> 2);
                uint32_t r0 = __shfl_sync(0xffffffffu, ehi[0], src);
                uint32_t r1 = __shfl_sync(0xffffffffu, ehi[1], src);
                uint32_t r2 = __shfl_sync(0xffffffffu, ehi[2], src);
                uint32_t r3 = __shfl_sync(0xffffffffu, ehi[3], src);
                uint32_t s01 = b0sel ? r1 : r0, s23 = b0sel ? r3 : r2;
                Ah[m][h] = b1sel ? s23 : s01;
                r0 = __shfl_sync(0xffffffffu, elo[0], src);
                r1 = __shfl_sync(0xffffffffu, elo[1], src);
                r2 = __shfl_sync(0xffffffffu, elo[2], src);
                r3 = __shfl_sync(0xffffffffu, elo[3], src);
                s01 = b0sel ? r1 : r0; s23 = b0sel ? r3 : r2;
                Al[m][h] = b1sel ? s23 : s01;
            }
        }

        // ---- layer 1: A1 [32 x 32] @ B1 [32 x 64] ----
        float d1[2][8][4];
        #pragma unroll
        for (int m = 0; m < 2; m++)
            #pragma unroll
            for (int j = 0; j < 8; j++)
                #pragma unroll
                for (int q = 0; q < 4; q++) d1[m][j][q] = 0.0f;

        #pragma unroll
        for (int j = 0; j < 8; j++) {
            uint2 bA = sF[(0 * 8 + j) * 32 + lane];
            uint2 bB = sF[(1 * 8 + j) * 32 + lane];
            #pragma unroll
            for (int m = 0; m < 2; m++) {
                mma16816(d1[m][j], Ah[m][0], Ah[m][1], Al[m][0], Al[m][1], bA.x, bA.y);
                mma16816(d1[m][j], Ah[m][0], Ah[m][1], 0u, 0u, bB.x, bB.y);
            }
        }

        // ---- epilogue 1: leaky, split hi/lo; D frags become A frags ----
        uint32_t A2h[2][8][2], A2l[2][8][2];
        #pragma unroll
        for (int m = 0; m < 2; m++) {
            #pragma unroll
            for (int j = 0; j < 8; j++) {
                float x0 = leaky(d1[m][j][0]), x1 = leaky(d1[m][j][1]);
                float x2 = leaky(d1[m][j][2]), x3 = leaky(d1[m][j][3]);
                uint32_t p0 = pack_f16x2(x0, x1);
                uint32_t p1 = pack_f16x2(x2, x3);
                A2h[m][j][0] = p0;
                A2h[m][j][1] = p1;
                float h0, h1;
                unpack_f16x2(p0, h0, h1);
                A2l[m][j][0] = pack_f16x2(x0 - h0, x1 - h1);
                unpack_f16x2(p1, h0, h1);
                A2l[m][j][1] = pack_f16x2(x2 - h0, x3 - h1);
            }
        }

        // ---- layer 2: A2 [32 x 192] @ B2 [192 x 64] ----
        float d2[2][8][4];
        #pragma unroll
        for (int m = 0; m < 2; m++)
            #pragma unroll
            for (int j = 0; j < 8; j++)
                #pragma unroll
                for (int q = 0; q < 4; q++) d2[m][j][q] = 0.0f;

        #pragma unroll
        for (int t = 0; t < 12; t++) {
            const int tp = (t < 4) ? t : ((t < 8) ? (t - 4) : (t - 8));
            const bool useLo = (t >= 4 && t < 8);
            #pragma unroll
            for (int j = 0; j < 8; j++) {
                uint2 b = sF[(16 + t * 8 + j) * 32 + lane];
                #pragma unroll
                for (int m = 0; m < 2; m++) {
                    uint32_t a0, a1, a2, a3;
                    if (useLo) {
                        a0 = A2l[m][2 * tp][0]; a1 = A2l[m][2 * tp][1];
                        a2 = A2l[m][2 * tp + 1][0]; a3 = A2l[m][2 * tp + 1][1];
                    } else {
                        a0 = A2h[m][2 * tp][0]; a1 = A2h[m][2 * tp][1];
                        a2 = A2h[m][2 * tp + 1][0]; a3 = A2h[m][2 * tp + 1][1];
                    }
                    mma16816(d2[m][j], a0, a1, a2, a3, b.x, b.y);
                }
            }
        }

        // ---- layer 3: leaky(D2) . W_out, lane-group reduce, store ----
        #pragma unroll
        for (int m = 0; m < 2; m++) {
            float accL = 0.0f, accH = 0.0f;
            #pragma unroll
            for (int j = 0; j < 8; j++) {
                accL = fmaf(leaky(d2[m][j][0]), wo0[j], accL);
                accL = fmaf(leaky(d2[m][j][1]), wo1[j], accL);
                accH = fmaf(leaky(d2[m][j][2]), wo0[j], accH);
                accH = fmaf(leaky(d2[m][j][3]), wo1[j], accH);
            }
            accL += __shfl_xor_sync(0xffffffffu, accL, 1);
            accL += __shfl_xor_sync(0xffffffffu, accL, 2);
            accH += __shfl_xor_sync(0xffffffffu, accH, 1);
            accH += __shfl_xor_sync(0xffffffffu, accH, 2);
            if ((lane & 3) == 0) {
                int p = tile * 128 + wid * 32 + m * 16 + (lane >> 2);
                if (p < N)     out[p] = accL * 0.1f;
                if (p + 8 < N) out[p + 8] = accH * 0.1f;
            }
        }
    }
}

extern "C" void kernel_launch(void* const* d_in, const int* in_sizes, int n_in,
                              void* d_out, int out_size) {
    const float* xyz    = (const float*)d_in[0];
    const float* tables = (const float*)d_in[1];
    const float* W_in   = (const float*)d_in[2];
    const float* W_h    = (const float*)d_in[3];
    const float* W_out  = (const float*)d_in[4];
    float* out = (float*)d_out;

    int N = in_sizes[0] / 3;
    int numTiles = (N + 127) / 128;

    encode_kernel<<<(N + 255) / 256, 256>>>(xyz, tables, W_in, W_h, N);

    int mlpGrid = numTiles < 296 ? numTiles : 296;   // 2 CTAs/SM x 148
    mlp_kernel<<<mlpGrid, 128>>>(W_out, out, N, numTiles);
}

// round 17
// speedup vs baseline: 1.5630x; 1.5630x over previous
#include <cuda_runtime.h>
#include <cuda_fp16.h>
#include <cstdint>

// ResidualNet: hash-grid encode (4 levels, T=2^19, F=2) + MLP 8->64->64->1
//   d_in[0] xyz [N,3] f32 (N=2,000,000), d_in[1] tables [4,524288,2] f32,
//   d_in[2] W_in [8,64], d_in[3] W_h [64,64], d_in[4] W_out [64,1]
// Output: sdf [N] f32
//
// Round-14 proven kernels (bodies untouched), now chunk-pipelined across two
// streams inside the captured graph: encode chunk k (L1tex-bound) overlaps
// mlp chunk k-1 (tensor-bound). prep overlaps encode chunk 0.

#define TSIZE (1u << 19)
#define TMASK (TSIZE - 1u)
#define P2 2654435761u
#define P3 805459861u
#define NMAX  2000000
#define NCHUNK 4

// staged enc: per point 8 u32 = [ehi0..3, elo0..3] (f16x2 each)
static __device__ __align__(16) uint32_t g_enc[(size_t)NMAX * 8];
// precomputed B fragments: 112 slots (B1: slots 0..15; B2: 16 + t*8 + n)
static __device__ __align__(16) uint2 g_frags[112 * 32];

__device__ __forceinline__ float leaky(float v) { return fmaxf(v, 0.01f * v); }

__device__ __forceinline__ uint32_t pack_f16x2(float lo, float hi) {
    uint32_t r;
    asm("cvt.rn.f16x2.f32 %0, %1, %2;" : "=r"(r) : "f"(hi), "f"(lo));
    return r;
}
__device__ __forceinline__ void unpack_f16x2(uint32_t v, float& lo, float& hi) {
    asm("{ .reg .f16 a,b; mov.b32 {a,b}, %2; cvt.f32.f16 %0, a; cvt.f32.f16 %1, b; }"
        : "=f"(lo), "=f"(hi) : "r"(v));
}

__device__ __forceinline__ void mma16816(float* d,
                                         uint32_t a0, uint32_t a1, uint32_t a2, uint32_t a3,
                                         uint32_t b0, uint32_t b1) {
    asm volatile("mma.sync.aligned.m16n8k16.row.col.f32.f16.f16.f32 "
                 "{%0,%1,%2,%3}, {%4,%5,%6,%7}, {%8,%9}, {%0,%1,%2,%3};"
                 : "+f"(d[0]), "+f"(d[1]), "+f"(d[2]), "+f"(d[3])
                 : "r"(a0), "r"(a1), "r"(a2), "r"(a3), "r"(b0), "r"(b1));
}

// ---------------------------------------------------------------------------
// prep: build per-lane B fragments in mma.m16n8k16 col-major layout.
// B1 expanded K=32 rows: [hi(W_in), hi(W_in), lo(W_in), 0]  (A1=[hi,lo,hi,0])
// B2 expanded K=192:     [hi(W_h), hi(W_h), lo(W_h)]        (A2=[hi,lo,hi])
// ---------------------------------------------------------------------------
extern "C" __global__ void prep_kernel(const float* __restrict__ W_in,
                                       const float* __restrict__ W_h)
{
    int idx = blockIdx.x * blockDim.x + threadIdx.x;
    if (idx >= 112 * 32) return;
    int lane = idx & 31, s = idx >> 5;
    int n = (s & 7) * 8 + (lane >> 2);
    uint32_t b[2];
    #pragma unroll
    for (int w = 0; w < 2; w++) {
        __half hv[2];
        #pragma unroll
        for (int e = 0; e < 2; e++) {
            int kr = (lane & 3) * 2 + e + w * 8;
            float val = 0.0f;
            bool want_lo = false;
            bool zero = false;
            if (s < 16) {
                int kk = (s >> 3) * 16 + kr;             // 0..31
                if (kk < 8)       val = W_in[kk * 64 + n];
                else if (kk < 16) val = W_in[(kk - 8) * 64 + n];
                else if (kk < 24) { val = W_in[(kk - 16) * 64 + n]; want_lo = true; }
                else zero = true;
            } else {
                int kk = ((s - 16) >> 3) * 16 + kr;      // 0..191
                if (kk < 64)       val = W_h[kk * 64 + n];
                else if (kk < 128) val = W_h[(kk - 64) * 64 + n];
                else { val = W_h[(kk - 128) * 64 + n]; want_lo = true; }
            }
            __half h = __float2half_rn(val);
            if (want_lo) h = __float2half_rn(val - __half2float(h));
            if (zero) h = __float2half_rn(0.0f);
            hv[e] = h;
        }
        __half2 hh = __halves2half2(hv[0], hv[1]);
        b[w] = *reinterpret_cast<uint32_t*>(&hh);
    }
    g_frags[idx] = make_uint2(b[0], b[1]);
}

// ---------------------------------------------------------------------------
// encode (round-14 body): gather with x-pair merge over points [p0, p1)
// ---------------------------------------------------------------------------
extern "C" __global__ void __launch_bounds__(256, 4)
encode_kernel(const float* __restrict__ xyz,
              const float* __restrict__ tables,
              int p0, int p1)
{
    int i = p0 + blockIdx.x * 256 + threadIdx.x;
    if (i >= p1) return;

    float px = (xyz[3 * i + 0] + 5.0f) / 10.0f;
    float py = (xyz[3 * i + 1] + 5.0f) / 10.0f;
    float pz = (xyz[3 * i + 2] + 5.0f) / 10.0f;

    float enc[8];
    #pragma unroll
    for (int l = 0; l < 4; l++) {
        float res = (float)(200 << l);
        float fx = px * res, fy = py * res, fz = pz * res;
        float bx = floorf(fx), by = floorf(fy), bz = floorf(fz);
        float tx = fx - bx, ty = fy - by, tz = fz - bz;
        unsigned ux = (unsigned)bx, uy = (unsigned)by, uz = (unsigned)bz;
        const float2* tab = (const float2*)(tables + (size_t)l * TSIZE * 2u);
        float wx0 = 1.0f - tx, wx1 = tx;
        float wy[2] = {1.0f - ty, ty};
        float wz[2] = {1.0f - tz, tz};
        unsigned Ky[2] = {uy * P2, (uy + 1) * P2};
        unsigned Kz[2] = {uz * P3, (uz + 1) * P3};
        const bool even = (ux & 1u) == 0u;

        float f0 = 0.0f, f1 = 0.0f;
        #pragma unroll
        for (int yy = 0; yy < 2; yy++) {
            #pragma unroll
            for (int zz = 0; zz < 2; zz++) {
                unsigned K = Ky[yy] ^ Kz[zz];
                unsigned i0 = (ux ^ K) & TMASK;
                float2 fa, fb;
                if (even) {
                    // idx(ux+1) = i0 ^ 1: both corners in one 16B-aligned pair
                    unsigned e = i0 & ~1u;
                    float4 v = __ldg((const float4*)(tab + e));
                    bool swp = (i0 & 1u) != 0u;
                    fa = swp ? make_float2(v.z, v.w) : make_float2(v.x, v.y);
                    fb = swp ? make_float2(v.x, v.y) : make_float2(v.z, v.w);
                } else {
                    unsigned i1 = ((ux + 1u) ^ K) & TMASK;
                    fa = __ldg(tab + i0);
                    fb = __ldg(tab + i1);
                }
                float wyz = wy[yy] * wz[zz];
                float wa = wx0 * wyz, wb = wx1 * wyz;
                f0 = fmaf(fa.x, wa, fmaf(fb.x, wb, f0));
                f1 = fmaf(fa.y, wa, fmaf(fb.y, wb, f1));
            }
        }
        enc[2 * l + 0] = f0;
        enc[2 * l + 1] = f1;
    }

    uint32_t eh[4], el[4];
    #pragma unroll
    for (int c = 0; c < 4; c++) {
        float x0 = enc[2 * c], x1 = enc[2 * c + 1];
        eh[c] = pack_f16x2(x0, x1);
        float h0, h1;
        unpack_f16x2(eh[c], h0, h1);
        el[c] = pack_f16x2(x0 - h0, x1 - h1);
    }
    uint4* o = (uint4*)&g_enc[(size_t)i * 8];
    o[0] = make_uint4(eh[0], eh[1], eh[2], eh[3]);
    o[1] = make_uint4(el[0], el[1], el[2], el[3]);
}

// ---------------------------------------------------------------------------
// mlp (round-14 body): grid-stride over tiles [t0, t1); 32 points/warp HMMA.
// ---------------------------------------------------------------------------
extern "C" __global__ void __launch_bounds__(128, 2)
mlp_kernel(const float* __restrict__ W_out, float* __restrict__ out,
           int N, int t0, int t1)
{
    __shared__ uint2 sF[112 * 32];   // 28 KB B fragments

    const int tid = threadIdx.x;
    const int lane = tid & 31;
    const int wid = tid >> 5;

    // stage fragments once
    {
        const uint4* s = (const uint4*)g_frags;
        uint4* d = (uint4*)sF;
        #pragma unroll
        for (int k = tid; k < 112 * 32 / 2; k += 128) d[k] = s[k];
    }

    // W_out per-lane registers (loop-invariant)
    float wo0[8], wo1[8];
    #pragma unroll
    for (int j = 0; j < 8; j++) {
        float2 v = __ldg((const float2*)&W_out[j * 8 + (lane & 3) * 2]);
        wo0[j] = v.x; wo1[j] = v.y;
    }
    __syncthreads();  // fragments staged

    const bool b0sel = (lane & 1), b1sel = (lane & 2);

    for (int tile = t0 + blockIdx.x; tile < t1; tile += gridDim.x) {
        int i = tile * 128 + tid;
        int ic = i < N ? i : (N - 1);
        const uint4* ep = (const uint4*)&g_enc[(size_t)ic * 8];
        uint4 EH = ep[0], EL = ep[1];
        uint32_t ehi[4] = {EH.x, EH.y, EH.z, EH.w};
        uint32_t elo[4] = {EL.x, EL.y, EL.z, EL.w};

        // ---- build A1 fragment pieces via shuffles ----
        uint32_t Ah[2][2], Al[2][2];
        #pragma unroll
        for (int m = 0; m < 2; m++) {
            #pragma unroll
            for (int h = 0; h < 2; h++) {
                int src = m * 16 + h * 8 + (lane >> 2);
                uint32_t r0 = __shfl_sync(0xffffffffu, ehi[0], src);
                uint32_t r1 = __shfl_sync(0xffffffffu, ehi[1], src);
                uint32_t r2 = __shfl_sync(0xffffffffu, ehi[2], src);
                uint32_t r3 = __shfl_sync(0xffffffffu, ehi[3], src);
                uint32_t s01 = b0sel ? r1 : r0, s23 = b0sel ? r3 : r2;
                Ah[m][h] = b1sel ? s23 : s01;
                r0 = __shfl_sync(0xffffffffu, elo[0], src);
                r1 = __shfl_sync(0xffffffffu, elo[1], src);
                r2 = __shfl_sync(0xffffffffu, elo[2], src);
                r3 = __shfl_sync(0xffffffffu, elo[3], src);
                s01 = b0sel ? r1 : r0; s23 = b0sel ? r3 : r2;
                Al[m][h] = b1sel ? s23 : s01;
            }
        }

        // ---- layer 1: A1 [32 x 32] @ B1 [32 x 64] ----
        float d1[2][8][4];
        #pragma unroll
        for (int m = 0; m < 2; m++)
            #pragma unroll
            for (int j = 0; j < 8; j++)
                #pragma unroll
                for (int q = 0; q < 4; q++) d1[m][j][q] = 0.0f;

        #pragma unroll
        for (int j = 0; j < 8; j++) {
            uint2 bA = sF[(0 * 8 + j) * 32 + lane];
            uint2 bB = sF[(1 * 8 + j) * 32 + lane];
            #pragma unroll
            for (int m = 0; m < 2; m++) {
                mma16816(d1[m][j], Ah[m][0], Ah[m][1], Al[m][0], Al[m][1], bA.x, bA.y);
                mma16816(d1[m][j], Ah[m][0], Ah[m][1], 0u, 0u, bB.x, bB.y);
            }
        }

        // ---- epilogue 1: leaky, split hi/lo; D frags become A frags ----
        uint32_t A2h[2][8][2], A2l[2][8][2];
        #pragma unroll
        for (int m = 0; m < 2; m++) {
            #pragma unroll
            for (int j = 0; j < 8; j++) {
                float x0 = leaky(d1[m][j][0]), x1 = leaky(d1[m][j][1]);
                float x2 = leaky(d1[m][j][2]), x3 = leaky(d1[m][j][3]);
                uint32_t p0 = pack_f16x2(x0, x1);
                uint32_t p1 = pack_f16x2(x2, x3);
                A2h[m][j][0] = p0;
                A2h[m][j][1] = p1;
                float h0, h1;
                unpack_f16x2(p0, h0, h1);
                A2l[m][j][0] = pack_f16x2(x0 - h0, x1 - h1);
                unpack_f16x2(p1, h0, h1);
                A2l[m][j][1] = pack_f16x2(x2 - h0, x3 - h1);
            }
        }

        // ---- layer 2: A2 [32 x 192] @ B2 [192 x 64] ----
        float d2[2][8][4];
        #pragma unroll
        for (int m = 0; m < 2; m++)
            #pragma unroll
            for (int j = 0; j < 8; j++)
                #pragma unroll
                for (int q = 0; q < 4; q++) d2[m][j][q] = 0.0f;

        #pragma unroll
        for (int t = 0; t < 12; t++) {
            const int tp = (t < 4) ? t : ((t < 8) ? (t - 4) : (t - 8));
            const bool useLo = (t >= 4 && t < 8);
            #pragma unroll
            for (int j = 0; j < 8; j++) {
                uint2 b = sF[(16 + t * 8 + j) * 32 + lane];
                #pragma unroll
                for (int m = 0; m < 2; m++) {
                    uint32_t a0, a1, a2, a3;
                    if (useLo) {
                        a0 = A2l[m][2 * tp][0]; a1 = A2l[m][2 * tp][1];
                        a2 = A2l[m][2 * tp + 1][0]; a3 = A2l[m][2 * tp + 1][1];
                    } else {
                        a0 = A2h[m][2 * tp][0]; a1 = A2h[m][2 * tp][1];
                        a2 = A2h[m][2 * tp + 1][0]; a3 = A2h[m][2 * tp + 1][1];
                    }
                    mma16816(d2[m][j], a0, a1, a2, a3, b.x, b.y);
                }
            }
        }

        // ---- layer 3: leaky(D2) . W_out, lane-group reduce, store ----
        #pragma unroll
        for (int m = 0; m < 2; m++) {
            float accL = 0.0f, accH = 0.0f;
            #pragma unroll
            for (int j = 0; j < 8; j++) {
                accL = fmaf(leaky(d2[m][j][0]), wo0[j], accL);
                accL = fmaf(leaky(d2[m][j][1]), wo1[j], accL);
                accH = fmaf(leaky(d2[m][j][2]), wo0[j], accH);
                accH = fmaf(leaky(d2[m][j][3]), wo1[j], accH);
            }
            accL += __shfl_xor_sync(0xffffffffu, accL, 1);
            accL += __shfl_xor_sync(0xffffffffu, accL, 2);
            accH += __shfl_xor_sync(0xffffffffu, accH, 1);
            accH += __shfl_xor_sync(0xffffffffu, accH, 2);
            if ((lane & 3) == 0) {
                int p = tile * 128 + wid * 32 + m * 16 + (lane >> 2);
                if (p < N)     out[p] = accL * 0.1f;
                if (p + 8 < N) out[p + 8] = accH * 0.1f;
            }
        }
    }
}

extern "C" void kernel_launch(void* const* d_in, const int* in_sizes, int n_in,
                              void* d_out, int out_size) {
    const float* xyz    = (const float*)d_in[0];
    const float* tables = (const float*)d_in[1];
    const float* W_in   = (const float*)d_in[2];
    const float* W_h    = (const float*)d_in[3];
    const float* W_out  = (const float*)d_in[4];
    float* out = (float*)d_out;

    int N = in_sizes[0] / 3;

    // Lazy one-time stream/event creation (resources only; the WORK below is
    // identical on every call). Falls back to sequential if unavailable.
    static cudaStream_t sB = nullptr;
    static cudaEvent_t evFork = nullptr, evDone = nullptr, ev[NCHUNK];
    static bool triedInit = false;
    if (!triedInit) {
        triedInit = true;
        bool ok = (cudaStreamCreateWithFlags(&sB, cudaStreamNonBlocking) == cudaSuccess);
        ok = ok && (cudaEventCreateWithFlags(&evFork, cudaEventDisableTiming) == cudaSuccess);
        ok = ok && (cudaEventCreateWithFlags(&evDone, cudaEventDisableTiming) == cudaSuccess);
        for (int k = 0; k < NCHUNK && ok; k++)
            ok = ok && (cudaEventCreateWithFlags(&ev[k], cudaEventDisableTiming) == cudaSuccess);
        if (!ok) sB = nullptr;
    }

    if (sB) {
        // fork second stream off the capture-origin stream
        cudaEventRecord(evFork, 0);
        cudaStreamWaitEvent(sB, evFork, 0);
        prep_kernel<<<7, 512, 0, sB>>>(W_in, W_h);

        int chunk = (((N + NCHUNK - 1) / NCHUNK) + 255) & ~255;
        for (int k = 0; k < NCHUNK; k++) {
            int p0 = k * chunk;
            if (p0 >= N) break;
            int p1 = p0 + chunk; if (p1 > N) p1 = N;
            int pts = p1 - p0;
            encode_kernel<<<(pts + 255) / 256, 256>>>(xyz, tables, p0, p1);
            cudaEventRecord(ev[k], 0);
            cudaStreamWaitEvent(sB, ev[k], 0);
            int t0 = p0 / 128;                    // chunk is 256-aligned
            int t1 = (p1 + 127) / 128;
            int g = t1 - t0; if (g > 296) g = 296;
            mlp_kernel<<<g, 128, 0, sB>>>(W_out, out, N, t0, t1);
        }
        // join: capture-origin stream waits for all mlp work
        cudaEventRecord(evDone, sB);
        cudaStreamWaitEvent(0, evDone, 0);
    } else {
        // sequential fallback (== round-14 pipeline)
        prep_kernel<<<7, 512>>>(W_in, W_h);
        encode_kernel<<<(N + 255) / 256, 256>>>(xyz, tables, 0, N);
        int numTiles = (N + 127) / 128;
        int g = numTiles < 296 ? numTiles : 296;
        mlp_kernel<<<g, 128>>>(W_out, out, N, 0, numTiles);
    }
}